// round 17
// baseline (speedup 1.0000x reference)
#include <cuda_runtime.h>
#include <math.h>
#include <stdint.h>

#define NUM_SEQS   64
#define NUM_HEADS  32
#define KVH        8
#define GQ         4      // query heads per kv head
#define HD         128    // head size
#define BS         16     // paged block size
#define MAXL       2048
#define MAXB       128    // max blocks per seq
#define PART       128    // tokens per split-KV partition
#define NP         (MAXL / PART)   // 16
#define NCHMAX     (PART / BS)     // 8 chunks (one paged block each)
#define NTHREADS   256
#define NWARPS     8
#define NBUF       4       // per-warp pipeline buffers (depth-3 overlap)
#define FULLMASK   0xffffffffu

// Split-KV scratch (device globals)
__device__ float g_pacc[NUM_SEQS * KVH * NP * GQ * HD];
__device__ float g_pl[NUM_SEQS * KVH * NP * GQ];
__device__ int   g_cnt[NUM_SEQS * KVH];    // zero-initialized; self-cleaning

struct AccState {
    float4 a0, a1, a2, a3;
    float  lsum;           // per-lane: sum of e for head (lane&3)
};

// One token: dot for 4 heads -> transposed butterfly (lane l ends with the
// COMPLETE score of head l&3) -> single exp/lane -> broadcast -> V FMA.
__device__ __forceinline__ void token_step(
    AccState& st, const float4 k4, const float4 v4,
    const float4 qr0, const float4 qr1, const float4 qr2, const float4 qr3,
    const float rel, const float slp_lane, const int lane)
{
    float p0 = qr0.x*k4.x + qr0.y*k4.y + qr0.z*k4.z + qr0.w*k4.w;
    float p1 = qr1.x*k4.x + qr1.y*k4.y + qr1.z*k4.z + qr1.w*k4.w;
    float p2 = qr2.x*k4.x + qr2.y*k4.y + qr2.z*k4.z + qr2.w*k4.w;
    float p3 = qr3.x*k4.x + qr3.y*k4.y + qr3.z*k4.z + qr3.w*k4.w;

    const bool b0 = (lane & 1);
    float x01 = b0 ? p1 : p0;
    float y01 = b0 ? p0 : p1;
    x01 += __shfl_xor_sync(FULLMASK, y01, 1);
    float x23 = b0 ? p3 : p2;
    float y23 = b0 ? p2 : p3;
    x23 += __shfl_xor_sync(FULLMASK, y23, 1);
    const bool b1 = (lane & 2);
    float x = b1 ? x23 : x01;
    float y = b1 ? x01 : x23;
    x += __shfl_xor_sync(FULLMASK, y, 2);
    x += __shfl_xor_sync(FULLMASK, x, 4);
    x += __shfl_xor_sync(FULLMASK, x, 8);
    x += __shfl_xor_sync(FULLMASK, x, 16);

    const float e = __expf(fmaf(slp_lane, rel, x));
    st.lsum += e;

    const float e0 = __shfl_sync(FULLMASK, e, 0);
    const float e1 = __shfl_sync(FULLMASK, e, 1);
    const float e2 = __shfl_sync(FULLMASK, e, 2);
    const float e3 = __shfl_sync(FULLMASK, e, 3);

    st.a0.x += e0*v4.x; st.a0.y += e0*v4.y; st.a0.z += e0*v4.z; st.a0.w += e0*v4.w;
    st.a1.x += e1*v4.x; st.a1.y += e1*v4.y; st.a1.z += e1*v4.z; st.a1.w += e1*v4.w;
    st.a2.x += e2*v4.x; st.a2.y += e2*v4.y; st.a2.z += e2*v4.z; st.a2.w += e2*v4.w;
    st.a3.x += e3*v4.x; st.a3.y += e3*v4.y; st.a3.z += e3*v4.z; st.a3.w += e3*v4.w;
}

__device__ __forceinline__ void cpa16(uint32_t dst, const void* src) {
    asm volatile("cp.async.cg.shared.global [%0], [%1], 16;" :: "r"(dst), "l"(src));
}
#define CPA_COMMIT() asm volatile("cp.async.commit_group;" ::: "memory")
#define CPA_WAIT(n)  asm volatile("cp.async.wait_group %0;" :: "n"(n) : "memory")

// dynamic smem: wbuf[NWARPS][NBUF][4 rows][HD] = 8*4*4*128*4 = 65536 B
#define SMEM_BYTES (NWARPS * NBUF * 4 * HD * 4)
#define WB(w, b, r) ((((w) * NBUF + (b)) * 4 + (r)) * HD)

__global__ __launch_bounds__(NTHREADS)
void paged_attn_kernel(const float* __restrict__ q,
                       const float* __restrict__ kcache,
                       const float* __restrict__ vcache,
                       const float* __restrict__ scale_p,
                       const int*   __restrict__ btab,
                       const int*   __restrict__ seqlen,
                       const float* __restrict__ slopes,
                       float*       __restrict__ out)
{
    extern __shared__ float wbuf[];

    const int p    = blockIdx.x % NP;
    const int kv   = (blockIdx.x / NP) % KVH;
    const int s    = blockIdx.x / (NP * KVH);
    const int tid  = threadIdx.x;
    const int lane = tid & 31;
    const int warp = tid >> 5;

    const int len = seqlen[s];
    const int t0  = p * PART;
    if (t0 >= len) return;
    const int tmax = min(PART, len - t0);
    const int np   = (len + PART - 1) / PART;
    const float scale = scale_p[0];

    __shared__ float  wl[NWARPS][GQ];
    __shared__ size_t sbase[NCHMAX];
    __shared__ int    is_last;

    // red[NWARPS][GQ][HD] aliases the first 16 KB of wbuf (outside pipeline)
    float (*red)[GQ][HD] = (float (*)[GQ][HD]) wbuf;

    // Stage Q (scaled) and block row-bases
    for (int i = tid; i < GQ * HD; i += NTHREADS)
        (&red[0][0][0])[i] = q[(s * NUM_HEADS + kv * GQ) * HD + i] * scale;
    const int nch = (tmax + BS - 1) >> 4;
    if (tid < nch) {
        const size_t kvstride = (size_t)KVH * BS * HD;
        sbase[tid] = (size_t)btab[s * MAXB + (t0 >> 4) + tid] * kvstride
                   + (size_t)kv * BS * HD;
    }
    __syncthreads();

    const float4 qr0 = ((const float4*)&red[0][0][0])[lane];
    const float4 qr1 = ((const float4*)&red[0][1][0])[lane];
    const float4 qr2 = ((const float4*)&red[0][2][0])[lane];
    const float4 qr3 = ((const float4*)&red[0][3][0])[lane];
    __syncthreads();   // Q consumed; wbuf free for pipelines

    const float slp_lane = slopes[kv * GQ + (lane & 3)];
    const float relbase  = (float)(t0 - (len - 1));

    // Per-warp chunk copy: tokens (c*16 + warp*2, +1) are ADJACENT rows in
    // block c -> 1 KB K + 1 KB V; 2+2 cpa16 per lane; one commit group.
    auto copy_chunk = [&](int c, int buf) {
        const size_t row = sbase[c] + (size_t)(warp * 2) * HD;
        const char* ksrc = (const char*)(kcache + row) + lane * 16;
        const char* vsrc = (const char*)(vcache + row) + lane * 16;
        uint32_t kdst = (uint32_t)__cvta_generic_to_shared(&wbuf[WB(warp, buf, 0)]) + lane * 16;
        uint32_t vdst = (uint32_t)__cvta_generic_to_shared(&wbuf[WB(warp, buf, 2)]) + lane * 16;
        cpa16(kdst,       ksrc);
        cpa16(kdst + 512, ksrc + 512);
        cpa16(vdst,       vsrc);
        cpa16(vdst + 512, vsrc + 512);
        CPA_COMMIT();
    };

    // Prologue: fill depth-3
    copy_chunk(0, 0);
    if (nch > 1) copy_chunk(1, 1);
    if (nch > 2) copy_chunk(2, 2);

    AccState st;
    st.a0 = make_float4(0,0,0,0); st.a1 = make_float4(0,0,0,0);
    st.a2 = make_float4(0,0,0,0); st.a3 = make_float4(0,0,0,0);
    st.lsum = 0.f;

    // Barrier-free main loop, depth-3 per-warp pipeline.
    // At iter c: groups younger than c that may be pending = min(2, nch-1-c).
    for (int c = 0; c < nch; c++) {
        if (c + 2 < nch)      { CPA_WAIT(2); }
        else if (c + 1 < nch) { CPA_WAIT(1); }
        else                  { CPA_WAIT(0); }

        // Issue next copy BEFORE compute for maximum lead time.
        if (c + 3 < nch) copy_chunk(c + 3, (c + 3) % NBUF);

        const int b = c % NBUF;
        const int tl0 = c * BS + warp * 2;
        const int tl1 = tl0 + 1;
        if (tl0 < tmax) {
            const float4 k4 = ((const float4*)&wbuf[WB(warp, b, 0)])[lane];
            const float4 v4 = ((const float4*)&wbuf[WB(warp, b, 2)])[lane];
            token_step(st, k4, v4, qr0, qr1, qr2, qr3,
                       relbase + (float)tl0, slp_lane, lane);
        }
        if (tl1 < tmax) {
            const float4 k4 = ((const float4*)&wbuf[WB(warp, b, 1)])[lane];
            const float4 v4 = ((const float4*)&wbuf[WB(warp, b, 3)])[lane];
            token_step(st, k4, v4, qr0, qr1, qr2, qr3,
                       relbase + (float)tl1, slp_lane, lane);
        }
    }
    __syncthreads();   // all warps done before red aliases wbuf

    // Cross-warp reduction in smem.
    if (lane < GQ) wl[warp][lane] = st.lsum;
    ((float4*)&red[warp][0][0])[lane] = st.a0;
    ((float4*)&red[warp][1][0])[lane] = st.a1;
    ((float4*)&red[warp][2][0])[lane] = st.a2;
    ((float4*)&red[warp][3][0])[lane] = st.a3;
    __syncthreads();

    const int d  = tid & 127;
    const int g0 = tid >> 7;
    float r0 = 0.f, r1 = 0.f;
    #pragma unroll
    for (int w = 0; w < NWARPS; w++) {
        r0 += red[w][g0][d];
        r1 += red[w][g0 + 2][d];
    }

    const int    skv = s * KVH + kv;
    const size_t pb  = ((size_t)skv * NP + p) * GQ;
    g_pacc[(pb + g0)     * HD + d] = r0;
    g_pacc[(pb + g0 + 2) * HD + d] = r1;
    if (tid < GQ) {
        float L = 0.f;
        #pragma unroll
        for (int w = 0; w < NWARPS; w++) L += wl[w][tid];
        g_pl[pb + tid] = L;
    }

    // ---- Decoupled completion: last CTA for this (s, kv) combines ----
    __threadfence();
    __syncthreads();
    if (tid == 0)
        is_last = (atomicAdd(&g_cnt[skv], 1) == np - 1) ? 1 : 0;
    __syncthreads();
    if (!is_last) return;
    __threadfence();

    const size_t base = (size_t)skv * NP * GQ;
    float L0 = 0.f, L1 = 0.f, o0 = 0.f, o1 = 0.f;
    for (int pp = 0; pp < np; pp++) {
        const size_t i0 = base + (size_t)pp * GQ + g0;
        const size_t i1 = i0 + 2;
        L0 += g_pl[i0];
        L1 += g_pl[i1];
        o0 += g_pacc[i0 * HD + d];
        o1 += g_pacc[i1 * HD + d];
    }
    out[(size_t)(s * NUM_HEADS + kv * GQ + g0)     * HD + d] = o0 / L0;
    out[(size_t)(s * NUM_HEADS + kv * GQ + g0 + 2) * HD + d] = o1 / L1;

    if (tid == 0) g_cnt[skv] = 0;
}

extern "C" void kernel_launch(void* const* d_in, const int* in_sizes, int n_in,
                              void* d_out, int out_size) {
    const float* query       = (const float*)d_in[0];
    const float* key_cache   = (const float*)d_in[1];
    const float* value_cache = (const float*)d_in[2];
    const float* scale       = (const float*)d_in[4];
    const int*   block_tab   = (const int*)  d_in[5];
    const int*   seq_lens    = (const int*)  d_in[6];
    const float* alibi       = (const float*)d_in[9];
    float* out = (float*)d_out;

    cudaFuncSetAttribute(paged_attn_kernel,
                         cudaFuncAttributeMaxDynamicSharedMemorySize, SMEM_BYTES);
    paged_attn_kernel<<<NUM_SEQS * KVH * NP, NTHREADS, SMEM_BYTES>>>(
        query, key_cache, value_cache, scale, block_tab, seq_lens, alibi, out);
}